// round 1
// baseline (speedup 1.0000x reference)
#include <cuda_runtime.h>
#include <cuda_bf16.h>

#define Nn 20000
#define Ee 320000
#define EP (Ee + Nn)      // edges + self loops = 340000
#define Bb 128
#define CAT 576

// ---------------- scratch (static __device__, no allocation) ----------------
__device__ float g_H1[Nn * 512];      // encoder hidden
__device__ float g_H [Nn * 64];       // encoder out
__device__ float g_XL[Nn * 256];      // per-layer source transform (reused)
__device__ float g_XR[Nn * 256];      // per-layer target transform (reused)
__device__ float g_C1[Nn * 256];      // conv1 out (relu)
__device__ float g_C2[Nn * 256];      // conv2 out (relu)
__device__ int   g_deg[Nn];
__device__ int   g_rowptr[Nn + 1];
__device__ int   g_cursor[Nn];
__device__ int   g_col[EP];
__device__ float g_feat[Bb * CAT];

// ---------------- generic tiled SGEMM + bias + optional relu ----------------
// C[M,N] = act(A[M,K] @ W[K,N] + bias[N]);  N multiple of 64, K multiple of 16.
__global__ __launch_bounds__(256) void gemm_kernel(
    const float* __restrict__ A, const float* __restrict__ W,
    const float* __restrict__ bias, float* __restrict__ C,
    int M, int N, int K, int do_relu)
{
    __shared__ float As[16][65];
    __shared__ float Bs[16][64];

    int tid = threadIdx.x;
    int tx = tid & 15, ty = tid >> 4;
    int row0 = blockIdx.y * 64, col0 = blockIdx.x * 64;

    float acc[4][4];
#pragma unroll
    for (int m = 0; m < 4; m++)
#pragma unroll
        for (int n = 0; n < 4; n++) acc[m][n] = 0.f;

    for (int k0 = 0; k0 < K; k0 += 16) {
#pragma unroll
        for (int i = tid; i < 64 * 16; i += 256) {
            int r = i >> 4, c = i & 15;
            int gr = row0 + r;
            As[c][r] = (gr < M) ? A[(size_t)gr * K + k0 + c] : 0.f;
        }
#pragma unroll
        for (int i = tid; i < 16 * 64; i += 256) {
            int r = i >> 6, c = i & 63;
            Bs[r][c] = W[(size_t)(k0 + r) * N + col0 + c];
        }
        __syncthreads();
#pragma unroll
        for (int k = 0; k < 16; k++) {
            float ra[4], rb[4];
#pragma unroll
            for (int m = 0; m < 4; m++) ra[m] = As[k][ty * 4 + m];
#pragma unroll
            for (int n = 0; n < 4; n++) rb[n] = Bs[k][tx * 4 + n];
#pragma unroll
            for (int m = 0; m < 4; m++)
#pragma unroll
                for (int n = 0; n < 4; n++) acc[m][n] = fmaf(ra[m], rb[n], acc[m][n]);
        }
        __syncthreads();
    }
#pragma unroll
    for (int m = 0; m < 4; m++) {
        int gr = row0 + ty * 4 + m;
        if (gr < M) {
#pragma unroll
            for (int n = 0; n < 4; n++) {
                int gc = col0 + tx * 4 + n;
                float v = acc[m][n] + bias[gc];
                if (do_relu) v = fmaxf(v, 0.f);
                C[(size_t)gr * N + gc] = v;
            }
        }
    }
}

// ---------------- CSR build ----------------
__global__ void zero_deg_kernel() {
    int i = blockIdx.x * blockDim.x + threadIdx.x;
    if (i < Nn) g_deg[i] = 0;
}

__global__ void count_kernel(const int* __restrict__ ei) {
    int e = blockIdx.x * blockDim.x + threadIdx.x;
    if (e >= EP) return;
    int d = (e < Ee) ? ei[Ee + e] : (e - Ee);
    atomicAdd(&g_deg[d], 1);
}

__global__ __launch_bounds__(1024) void scan_kernel() {
    __shared__ int s[1024];
    int tid = threadIdx.x;
    const int chunk = (Nn + 1023) / 1024;   // 20
    int start = tid * chunk;
    int sum = 0;
    for (int i = 0; i < chunk; i++) {
        int idx = start + i;
        if (idx < Nn) sum += g_deg[idx];
    }
    s[tid] = sum;
    __syncthreads();
    for (int off = 1; off < 1024; off <<= 1) {
        int v = (tid >= off) ? s[tid - off] : 0;
        __syncthreads();
        s[tid] += v;
        __syncthreads();
    }
    int run = (tid > 0) ? s[tid - 1] : 0;
    for (int i = 0; i < chunk; i++) {
        int idx = start + i;
        if (idx < Nn) { g_rowptr[idx] = run; g_cursor[idx] = run; run += g_deg[idx]; }
    }
    if (tid == 1023) g_rowptr[Nn] = s[1023];
}

__global__ void scatter_kernel(const int* __restrict__ ei) {
    int e = blockIdx.x * blockDim.x + threadIdx.x;
    if (e >= EP) return;
    int s, d;
    if (e < Ee) { s = ei[e]; d = ei[Ee + e]; }
    else        { s = e - Ee; d = s; }
    int pos = atomicAdd(&g_cursor[d], 1);
    g_col[pos] = s;
}

// ---------------- GATv2 aggregation: one warp per destination node ----------
__device__ __forceinline__ float lrelu(float v) { return v > 0.f ? v : 0.2f * v; }

__global__ __launch_bounds__(256) void gat_agg_kernel(
    const float* __restrict__ XL, const float* __restrict__ XR,
    const float* __restrict__ att, const float* __restrict__ bias,
    float* __restrict__ OUT)
{
    int warp = (blockIdx.x * blockDim.x + threadIdx.x) >> 5;
    if (warp >= Nn) return;
    int lane = threadIdx.x & 31;

    // lane covers dims [lane*8, lane*8+8); all 8 dims within one head (head = lane/8)
    const float4* xr4 = reinterpret_cast<const float4*>(XR + (size_t)warp * 256 + lane * 8);
    float4 xr0 = xr4[0], xr1 = xr4[1];
    const float4* at4 = reinterpret_cast<const float4*>(att + lane * 8);
    float4 at0 = at4[0], at1 = at4[1];

    int s0 = g_rowptr[warp], s1 = g_rowptr[warp + 1];

    // pass A: per-head max score
    float mx = -3.0e38f;
    for (int slot = s0; slot < s1; slot++) {
        int src = g_col[slot];
        const float4* xl4 = reinterpret_cast<const float4*>(XL + (size_t)src * 256 + lane * 8);
        float4 a = xl4[0], b = xl4[1];
        float p = 0.f;
        p = fmaf(at0.x, lrelu(a.x + xr0.x), p);
        p = fmaf(at0.y, lrelu(a.y + xr0.y), p);
        p = fmaf(at0.z, lrelu(a.z + xr0.z), p);
        p = fmaf(at0.w, lrelu(a.w + xr0.w), p);
        p = fmaf(at1.x, lrelu(b.x + xr1.x), p);
        p = fmaf(at1.y, lrelu(b.y + xr1.y), p);
        p = fmaf(at1.z, lrelu(b.z + xr1.z), p);
        p = fmaf(at1.w, lrelu(b.w + xr1.w), p);
        p += __shfl_xor_sync(0xffffffffu, p, 1);
        p += __shfl_xor_sync(0xffffffffu, p, 2);
        p += __shfl_xor_sync(0xffffffffu, p, 4);
        mx = fmaxf(mx, p);
    }

    // pass B: denom = sum(exp), acc = sum(exp * xl)
    float denom = 0.f;
    float acc[8] = {0.f, 0.f, 0.f, 0.f, 0.f, 0.f, 0.f, 0.f};
    for (int slot = s0; slot < s1; slot++) {
        int src = g_col[slot];
        const float4* xl4 = reinterpret_cast<const float4*>(XL + (size_t)src * 256 + lane * 8);
        float4 a = xl4[0], b = xl4[1];
        float p = 0.f;
        p = fmaf(at0.x, lrelu(a.x + xr0.x), p);
        p = fmaf(at0.y, lrelu(a.y + xr0.y), p);
        p = fmaf(at0.z, lrelu(a.z + xr0.z), p);
        p = fmaf(at0.w, lrelu(a.w + xr0.w), p);
        p = fmaf(at1.x, lrelu(b.x + xr1.x), p);
        p = fmaf(at1.y, lrelu(b.y + xr1.y), p);
        p = fmaf(at1.z, lrelu(b.z + xr1.z), p);
        p = fmaf(at1.w, lrelu(b.w + xr1.w), p);
        p += __shfl_xor_sync(0xffffffffu, p, 1);
        p += __shfl_xor_sync(0xffffffffu, p, 2);
        p += __shfl_xor_sync(0xffffffffu, p, 4);
        float ex = __expf(p - mx);
        denom += ex;
        acc[0] = fmaf(ex, a.x, acc[0]);
        acc[1] = fmaf(ex, a.y, acc[1]);
        acc[2] = fmaf(ex, a.z, acc[2]);
        acc[3] = fmaf(ex, a.w, acc[3]);
        acc[4] = fmaf(ex, b.x, acc[4]);
        acc[5] = fmaf(ex, b.y, acc[5]);
        acc[6] = fmaf(ex, b.z, acc[6]);
        acc[7] = fmaf(ex, b.w, acc[7]);
    }

    float inv = 1.0f / (denom + 1e-16f);
    const float4* bi4 = reinterpret_cast<const float4*>(bias + lane * 8);
    float4 bb0 = bi4[0], bb1 = bi4[1];
    float4 o0, o1;
    o0.x = fmaxf(acc[0] * inv + bb0.x, 0.f);
    o0.y = fmaxf(acc[1] * inv + bb0.y, 0.f);
    o0.z = fmaxf(acc[2] * inv + bb0.z, 0.f);
    o0.w = fmaxf(acc[3] * inv + bb0.w, 0.f);
    o1.x = fmaxf(acc[4] * inv + bb1.x, 0.f);
    o1.y = fmaxf(acc[5] * inv + bb1.y, 0.f);
    o1.z = fmaxf(acc[6] * inv + bb1.z, 0.f);
    o1.w = fmaxf(acc[7] * inv + bb1.w, 0.f);
    float4* out4 = reinterpret_cast<float4*>(OUT + (size_t)warp * 256 + lane * 8);
    out4[0] = o0;
    out4[1] = o1;
}

// ---------------- batch gather + dueling head ----------------
__global__ void gather_feat_kernel(const int* __restrict__ idx) {
    int i = blockIdx.x * blockDim.x + threadIdx.x;
    if (i >= Bb * CAT) return;
    int b = i / CAT, j = i % CAT;
    int node = idx[b];
    float v;
    if (j < 64)       v = g_H [node * 64 + j];
    else if (j < 320) v = g_C1[node * 256 + (j - 64)];
    else              v = g_C2[node * 256 + (j - 320)];
    g_feat[i] = v;
}

__global__ __launch_bounds__(128) void duel_kernel(
    const float* __restrict__ qw1, const float* __restrict__ qb1,
    const float* __restrict__ qw2, const float* __restrict__ qb2,
    const float* __restrict__ vw1, const float* __restrict__ vb1,
    const float* __restrict__ vw2, const float* __restrict__ vb2,
    float* __restrict__ out)
{
    int b = blockIdx.x;
    int t = threadIdx.x;
    __shared__ float f[CAT];
    __shared__ float r0[128], r1[128], rv[128];
    for (int i = t; i < CAT; i += 128) f[i] = g_feat[b * CAT + i];
    __syncthreads();

    float sq = qb1[t], sv = vb1[t];
    for (int j = 0; j < CAT; j++) {
        float fv = f[j];
        sq = fmaf(fv, qw1[j * 128 + t], sq);
        sv = fmaf(fv, vw1[j * 128 + t], sv);
    }
    sq = fmaxf(sq, 0.f);
    sv = fmaxf(sv, 0.f);
    r0[t] = sq * qw2[t * 2 + 0];
    r1[t] = sq * qw2[t * 2 + 1];
    rv[t] = sv * vw2[t];
    __syncthreads();
    for (int off = 64; off > 0; off >>= 1) {
        if (t < off) {
            r0[t] += r0[t + off];
            r1[t] += r1[t + off];
            rv[t] += rv[t + off];
        }
        __syncthreads();
    }
    if (t == 0) {
        float q0 = r0[0] + qb2[0];
        float q1 = r1[0] + qb2[1];
        float v  = rv[0] + vb2[0];
        float m = 0.5f * (q0 + q1);
        out[b * 2 + 0] = q0 - m + v;
        out[b * 2 + 1] = q1 - m + v;
    }
}

// ---------------- host ----------------
extern "C" void kernel_launch(void* const* d_in, const int* in_sizes, int n_in,
                              void* d_out, int out_size)
{
    const float* x       = (const float*)d_in[0];
    const int*   ei      = (const int*)  d_in[1];
    const int*   indices = (const int*)  d_in[2];
    const float* enc_w1 = (const float*)d_in[3],  *enc_b1 = (const float*)d_in[4];
    const float* enc_w2 = (const float*)d_in[5],  *enc_b2 = (const float*)d_in[6];
    const float* wl1 = (const float*)d_in[7],  *bl1 = (const float*)d_in[8];
    const float* wr1 = (const float*)d_in[9],  *br1 = (const float*)d_in[10];
    const float* att1 = (const float*)d_in[11], *bias1 = (const float*)d_in[12];
    const float* wl2 = (const float*)d_in[13], *bl2 = (const float*)d_in[14];
    const float* wr2 = (const float*)d_in[15], *br2 = (const float*)d_in[16];
    const float* att2 = (const float*)d_in[17], *bias2 = (const float*)d_in[18];
    const float* qw1 = (const float*)d_in[19], *qb1 = (const float*)d_in[20];
    const float* qw2 = (const float*)d_in[21], *qb2 = (const float*)d_in[22];
    const float* vw1 = (const float*)d_in[23], *vb1 = (const float*)d_in[24];
    const float* vw2 = (const float*)d_in[25], *vb2 = (const float*)d_in[26];

    float *pH1, *pH, *pXL, *pXR, *pC1, *pC2;
    cudaGetSymbolAddress((void**)&pH1, g_H1);
    cudaGetSymbolAddress((void**)&pH,  g_H);
    cudaGetSymbolAddress((void**)&pXL, g_XL);
    cudaGetSymbolAddress((void**)&pXR, g_XR);
    cudaGetSymbolAddress((void**)&pC1, g_C1);
    cudaGetSymbolAddress((void**)&pC2, g_C2);

    // CSR build (per-launch; deterministic topology, atomics only affect order)
    zero_deg_kernel<<<(Nn + 255) / 256, 256>>>();
    count_kernel<<<(EP + 255) / 256, 256>>>(ei);
    scan_kernel<<<1, 1024>>>();
    scatter_kernel<<<(EP + 255) / 256, 256>>>(ei);

    const int MB = (Nn + 63) / 64;   // 313 row-blocks

    // encoder
    gemm_kernel<<<dim3(512 / 64, MB), 256>>>(x,   enc_w1, enc_b1, pH1, Nn, 512, 64, 1);
    gemm_kernel<<<dim3(64  / 64, MB), 256>>>(pH1, enc_w2, enc_b2, pH,  Nn, 64, 512, 1);

    // conv1
    gemm_kernel<<<dim3(256 / 64, MB), 256>>>(pH, wl1, bl1, pXL, Nn, 256, 64, 0);
    gemm_kernel<<<dim3(256 / 64, MB), 256>>>(pH, wr1, br1, pXR, Nn, 256, 64, 0);
    gat_agg_kernel<<<Nn / 8, 256>>>(pXL, pXR, att1, bias1, pC1);

    // conv2
    gemm_kernel<<<dim3(256 / 64, MB), 256>>>(pC1, wl2, bl2, pXL, Nn, 256, 256, 0);
    gemm_kernel<<<dim3(256 / 64, MB), 256>>>(pC1, wr2, br2, pXR, Nn, 256, 256, 0);
    gat_agg_kernel<<<Nn / 8, 256>>>(pXL, pXR, att2, bias2, pC2);

    // head
    gather_feat_kernel<<<(Bb * CAT + 255) / 256, 256>>>(indices);
    duel_kernel<<<Bb, 128>>>(qw1, qb1, qw2, qb2, vw1, vb1, vw2, vb2, (float*)d_out);
}

// round 3
// speedup vs baseline: 1.3019x; 1.3019x over previous
#include <cuda_runtime.h>
#include <cuda_bf16.h>

#define Nn 20000
#define Ee 320000
#define EP (Ee + Nn)      // edges + self loops = 340000
#define Bb 128
#define CAT 576

// ---------------- scratch (static __device__, no allocation) ----------------
__device__ float g_H1[Nn * 512];      // encoder hidden
__device__ float g_H [Nn * 64];       // encoder out
__device__ float g_XL[Nn * 256];      // per-layer source transform (reused)
__device__ float g_XR[Nn * 256];      // per-layer target transform (reused)
__device__ float g_C1[Nn * 256];      // conv1 out (relu)
__device__ float g_C2[Nn * 256];      // conv2 out (relu)
__device__ int   g_deg[Nn];
__device__ int   g_rowptr[Nn + 1];
__device__ int   g_cursor[Nn];
__device__ int   g_col[EP];
__device__ float g_feat[Bb * CAT];

// ---------------- 3xTF32 tensor-core GEMM ------------------------------------
// C[M,N] = act(A[M,K] @ W[K,N] + bias[N]), fp32-class accuracy via error
// compensation: a = a_hi + a_lo (tf32 split); c += a_hi*b_lo + a_lo*b_hi + a_hi*b_hi.
// Block tile 128x64, K-chunk 32; 8 warps, warp tile 32x32 via mma.m16n8k8 tf32.
__device__ __forceinline__ void mma_tf32(float c[4],
                                         const unsigned a[4], const unsigned b[2]) {
    asm volatile(
        "mma.sync.aligned.m16n8k8.row.col.f32.tf32.tf32.f32 "
        "{%0,%1,%2,%3}, {%4,%5,%6,%7}, {%8,%9}, {%0,%1,%2,%3};\n"
        : "+f"(c[0]), "+f"(c[1]), "+f"(c[2]), "+f"(c[3])
        : "r"(a[0]), "r"(a[1]), "r"(a[2]), "r"(a[3]),
          "r"(b[0]), "r"(b[1]));
}

__device__ __forceinline__ unsigned f2tf32(float f) {
    unsigned u;
    asm("cvt.rna.tf32.f32 %0, %1;\n" : "=r"(u) : "f"(f));
    return u;
}

__global__ __launch_bounds__(256) void gemm_tf32_kernel(
    const float* __restrict__ A, const float* __restrict__ W,
    const float* __restrict__ bias, float* __restrict__ C,
    int M, int N, int K, int do_relu)
{
    __shared__ float As[128][36];   // [m][k]
    __shared__ float Bs[32][72];    // [k][n]

    const int tid  = threadIdx.x;
    const int warp = tid >> 5, lane = tid & 31;
    const int wm = warp & 3, wn = warp >> 2;     // warp tile: m = wm*32, n = wn*32
    const int lr = lane >> 2;                     // 0..7
    const int lc = lane & 3;                      // 0..3
    const int row0 = blockIdx.y * 128, col0 = blockIdx.x * 64;

    float acc[2][4][4];
#pragma unroll
    for (int mt = 0; mt < 2; mt++)
#pragma unroll
        for (int nt = 0; nt < 4; nt++)
#pragma unroll
            for (int i = 0; i < 4; i++) acc[mt][nt][i] = 0.f;

    for (int k0 = 0; k0 < K; k0 += 32) {
        // A tile: 128 rows x 32 cols = 1024 float4
#pragma unroll
        for (int i = tid; i < 1024; i += 256) {
            int r = i >> 3, c4 = i & 7;
            int gr = min(row0 + r, M - 1);
            float4 v = *(const float4*)(A + (size_t)gr * K + k0 + c4 * 4);
            *(float4*)&As[r][c4 * 4] = v;
        }
        // B tile: 32 rows x 64 cols = 512 float4
#pragma unroll
        for (int i = tid; i < 512; i += 256) {
            int r = i >> 4, c4 = i & 15;
            float4 v = *(const float4*)(W + (size_t)(k0 + r) * N + col0 + c4 * 4);
            *(float4*)&Bs[r][c4 * 4] = v;
        }
        __syncthreads();

#pragma unroll
        for (int kk = 0; kk < 32; kk += 8) {
            // load fp32 fragments
            float af[2][4];
#pragma unroll
            for (int mt = 0; mt < 2; mt++) {
                int r = wm * 32 + mt * 16 + lr;
                af[mt][0] = As[r][kk + lc];
                af[mt][1] = As[r + 8][kk + lc];
                af[mt][2] = As[r][kk + lc + 4];
                af[mt][3] = As[r + 8][kk + lc + 4];
            }
            float bf[4][2];
#pragma unroll
            for (int nt = 0; nt < 4; nt++) {
                int n = wn * 32 + nt * 8 + lr;
                bf[nt][0] = Bs[kk + lc][n];
                bf[nt][1] = Bs[kk + lc + 4][n];
            }
            // tf32 hi/lo split
            unsigned ahi[2][4], alo[2][4];
#pragma unroll
            for (int mt = 0; mt < 2; mt++)
#pragma unroll
                for (int i = 0; i < 4; i++) {
                    unsigned h = f2tf32(af[mt][i]);
                    ahi[mt][i] = h;
                    alo[mt][i] = f2tf32(af[mt][i] - __uint_as_float(h));
                }
            unsigned bhi[4][2], blo[4][2];
#pragma unroll
            for (int nt = 0; nt < 4; nt++)
#pragma unroll
                for (int i = 0; i < 2; i++) {
                    unsigned h = f2tf32(bf[nt][i]);
                    bhi[nt][i] = h;
                    blo[nt][i] = f2tf32(bf[nt][i] - __uint_as_float(h));
                }
            // 3-term compensated mma (small terms first)
#pragma unroll
            for (int mt = 0; mt < 2; mt++)
#pragma unroll
                for (int nt = 0; nt < 4; nt++) {
                    mma_tf32(acc[mt][nt], ahi[mt], blo[nt]);
                    mma_tf32(acc[mt][nt], alo[mt], bhi[nt]);
                    mma_tf32(acc[mt][nt], ahi[mt], bhi[nt]);
                }
        }
        __syncthreads();
    }

    // epilogue: c0 (r, 2lc) c1 (r, 2lc+1) c2 (r+8, 2lc) c3 (r+8, 2lc+1)
#pragma unroll
    for (int mt = 0; mt < 2; mt++) {
#pragma unroll
        for (int nt = 0; nt < 4; nt++) {
            int r = row0 + wm * 32 + mt * 16 + lr;
            int n = col0 + wn * 32 + nt * 8 + 2 * lc;
            float b0 = bias[n], b1 = bias[n + 1];
            float v0 = acc[mt][nt][0] + b0, v1 = acc[mt][nt][1] + b1;
            float v2 = acc[mt][nt][2] + b0, v3 = acc[mt][nt][3] + b1;
            if (do_relu) {
                v0 = fmaxf(v0, 0.f); v1 = fmaxf(v1, 0.f);
                v2 = fmaxf(v2, 0.f); v3 = fmaxf(v3, 0.f);
            }
            if (r < M)     *(float2*)(C + (size_t)r * N + n)       = make_float2(v0, v1);
            if (r + 8 < M) *(float2*)(C + (size_t)(r + 8) * N + n) = make_float2(v2, v3);
        }
    }
}

// ---------------- CSR build ----------------
__global__ void zero_deg_kernel() {
    int i = blockIdx.x * blockDim.x + threadIdx.x;
    if (i < Nn) g_deg[i] = 0;
}

__global__ void count_kernel(const int* __restrict__ ei) {
    int e = blockIdx.x * blockDim.x + threadIdx.x;
    if (e >= EP) return;
    int d = (e < Ee) ? ei[Ee + e] : (e - Ee);
    atomicAdd(&g_deg[d], 1);
}

__global__ __launch_bounds__(1024) void scan_kernel() {
    __shared__ int s[1024];
    int tid = threadIdx.x;
    const int chunk = (Nn + 1023) / 1024;   // 20
    int start = tid * chunk;
    int sum = 0;
    for (int i = 0; i < chunk; i++) {
        int idx = start + i;
        if (idx < Nn) sum += g_deg[idx];
    }
    s[tid] = sum;
    __syncthreads();
    for (int off = 1; off < 1024; off <<= 1) {
        int v = (tid >= off) ? s[tid - off] : 0;
        __syncthreads();
        s[tid] += v;
        __syncthreads();
    }
    int run = (tid > 0) ? s[tid - 1] : 0;
    for (int i = 0; i < chunk; i++) {
        int idx = start + i;
        if (idx < Nn) { g_rowptr[idx] = run; g_cursor[idx] = run; run += g_deg[idx]; }
    }
    if (tid == 1023) g_rowptr[Nn] = s[1023];
}

__global__ void scatter_kernel(const int* __restrict__ ei) {
    int e = blockIdx.x * blockDim.x + threadIdx.x;
    if (e >= EP) return;
    int s, d;
    if (e < Ee) { s = ei[e]; d = ei[Ee + e]; }
    else        { s = e - Ee; d = s; }
    int pos = atomicAdd(&g_cursor[d], 1);
    g_col[pos] = s;
}

// ------- GATv2 aggregation: one warp per dst node, single-pass online softmax
__device__ __forceinline__ float lrelu(float v) { return v > 0.f ? v : 0.2f * v; }

__global__ __launch_bounds__(256) void gat_agg_kernel(
    const float* __restrict__ XL, const float* __restrict__ XR,
    const float* __restrict__ att, const float* __restrict__ bias,
    float* __restrict__ OUT)
{
    int warp = (blockIdx.x * blockDim.x + threadIdx.x) >> 5;
    if (warp >= Nn) return;
    int lane = threadIdx.x & 31;

    // lane covers dims [lane*8, lane*8+8); head = lane/8 (HID=64 dims = 8 lanes)
    const float4* xr4 = reinterpret_cast<const float4*>(XR + (size_t)warp * 256 + lane * 8);
    float4 xr0 = xr4[0], xr1 = xr4[1];
    const float4* at4 = reinterpret_cast<const float4*>(att + lane * 8);
    float4 at0 = at4[0], at1 = at4[1];

    int s0 = g_rowptr[warp], s1 = g_rowptr[warp + 1];

    float m = -3.0e38f, denom = 0.f;
    float acc[8] = {0.f, 0.f, 0.f, 0.f, 0.f, 0.f, 0.f, 0.f};

    for (int slot = s0; slot < s1; slot++) {
        int src = g_col[slot];
        const float4* xl4 = reinterpret_cast<const float4*>(XL + (size_t)src * 256 + lane * 8);
        float4 a = xl4[0], b = xl4[1];
        float p = 0.f;
        p = fmaf(at0.x, lrelu(a.x + xr0.x), p);
        p = fmaf(at0.y, lrelu(a.y + xr0.y), p);
        p = fmaf(at0.z, lrelu(a.z + xr0.z), p);
        p = fmaf(at0.w, lrelu(a.w + xr0.w), p);
        p = fmaf(at1.x, lrelu(b.x + xr1.x), p);
        p = fmaf(at1.y, lrelu(b.y + xr1.y), p);
        p = fmaf(at1.z, lrelu(b.z + xr1.z), p);
        p = fmaf(at1.w, lrelu(b.w + xr1.w), p);
        p += __shfl_xor_sync(0xffffffffu, p, 1);
        p += __shfl_xor_sync(0xffffffffu, p, 2);
        p += __shfl_xor_sync(0xffffffffu, p, 4);

        // online softmax update
        float mnew = fmaxf(m, p);
        float sc = __expf(m - mnew);   // ==1 when no new max; ==0 on first edge
        float ex = __expf(p - mnew);
        m = mnew;
        denom = denom * sc + ex;
        acc[0] = fmaf(ex, a.x, acc[0] * sc);
        acc[1] = fmaf(ex, a.y, acc[1] * sc);
        acc[2] = fmaf(ex, a.z, acc[2] * sc);
        acc[3] = fmaf(ex, a.w, acc[3] * sc);
        acc[4] = fmaf(ex, b.x, acc[4] * sc);
        acc[5] = fmaf(ex, b.y, acc[5] * sc);
        acc[6] = fmaf(ex, b.z, acc[6] * sc);
        acc[7] = fmaf(ex, b.w, acc[7] * sc);
    }

    float inv = 1.0f / (denom + 1e-16f);
    const float4* bi4 = reinterpret_cast<const float4*>(bias + lane * 8);
    float4 bb0 = bi4[0], bb1 = bi4[1];
    float4 o0, o1;
    o0.x = fmaxf(acc[0] * inv + bb0.x, 0.f);
    o0.y = fmaxf(acc[1] * inv + bb0.y, 0.f);
    o0.z = fmaxf(acc[2] * inv + bb0.z, 0.f);
    o0.w = fmaxf(acc[3] * inv + bb0.w, 0.f);
    o1.x = fmaxf(acc[4] * inv + bb1.x, 0.f);
    o1.y = fmaxf(acc[5] * inv + bb1.y, 0.f);
    o1.z = fmaxf(acc[6] * inv + bb1.z, 0.f);
    o1.w = fmaxf(acc[7] * inv + bb1.w, 0.f);
    float4* out4 = reinterpret_cast<float4*>(OUT + (size_t)warp * 256 + lane * 8);
    out4[0] = o0;
    out4[1] = o1;
}

// ---------------- batch gather + dueling head ----------------
__global__ void gather_feat_kernel(const int* __restrict__ idx) {
    int i = blockIdx.x * blockDim.x + threadIdx.x;
    if (i >= Bb * CAT) return;
    int b = i / CAT, j = i % CAT;
    int node = idx[b];
    float v;
    if (j < 64)       v = g_H [node * 64 + j];
    else if (j < 320) v = g_C1[node * 256 + (j - 64)];
    else              v = g_C2[node * 256 + (j - 320)];
    g_feat[i] = v;
}

__global__ __launch_bounds__(128) void duel_kernel(
    const float* __restrict__ qw1, const float* __restrict__ qb1,
    const float* __restrict__ qw2, const float* __restrict__ qb2,
    const float* __restrict__ vw1, const float* __restrict__ vb1,
    const float* __restrict__ vw2, const float* __restrict__ vb2,
    float* __restrict__ out)
{
    int b = blockIdx.x;
    int t = threadIdx.x;
    __shared__ float f[CAT];
    __shared__ float r0[128], r1[128], rv[128];
    for (int i = t; i < CAT; i += 128) f[i] = g_feat[b * CAT + i];
    __syncthreads();

    float sq = qb1[t], sv = vb1[t];
    for (int j = 0; j < CAT; j++) {
        float fv = f[j];
        sq = fmaf(fv, qw1[j * 128 + t], sq);
        sv = fmaf(fv, vw1[j * 128 + t], sv);
    }
    sq = fmaxf(sq, 0.f);
    sv = fmaxf(sv, 0.f);
    r0[t] = sq * qw2[t * 2 + 0];
    r1[t] = sq * qw2[t * 2 + 1];
    rv[t] = sv * vw2[t];
    __syncthreads();
    for (int off = 64; off > 0; off >>= 1) {
        if (t < off) {
            r0[t] += r0[t + off];
            r1[t] += r1[t + off];
            rv[t] += rv[t + off];
        }
        __syncthreads();
    }
    if (t == 0) {
        float q0 = r0[0] + qb2[0];
        float q1 = r1[0] + qb2[1];
        float v  = rv[0] + vb2[0];
        float mth = 0.5f * (q0 + q1);
        out[b * 2 + 0] = q0 - mth + v;
        out[b * 2 + 1] = q1 - mth + v;
    }
}

// ---------------- host ----------------
extern "C" void kernel_launch(void* const* d_in, const int* in_sizes, int n_in,
                              void* d_out, int out_size)
{
    const float* x       = (const float*)d_in[0];
    const int*   ei      = (const int*)  d_in[1];
    const int*   indices = (const int*)  d_in[2];
    const float* enc_w1 = (const float*)d_in[3],  *enc_b1 = (const float*)d_in[4];
    const float* enc_w2 = (const float*)d_in[5],  *enc_b2 = (const float*)d_in[6];
    const float* wl1 = (const float*)d_in[7],  *bl1 = (const float*)d_in[8];
    const float* wr1 = (const float*)d_in[9],  *br1 = (const float*)d_in[10];
    const float* att1 = (const float*)d_in[11], *bias1 = (const float*)d_in[12];
    const float* wl2 = (const float*)d_in[13], *bl2 = (const float*)d_in[14];
    const float* wr2 = (const float*)d_in[15], *br2 = (const float*)d_in[16];
    const float* att2 = (const float*)d_in[17], *bias2 = (const float*)d_in[18];
    const float* qw1 = (const float*)d_in[19], *qb1 = (const float*)d_in[20];
    const float* qw2 = (const float*)d_in[21], *qb2 = (const float*)d_in[22];
    const float* vw1 = (const float*)d_in[23], *vb1 = (const float*)d_in[24];
    const float* vw2 = (const float*)d_in[25], *vb2 = (const float*)d_in[26];

    float *pH1, *pH, *pXL, *pXR, *pC1, *pC2;
    cudaGetSymbolAddress((void**)&pH1, g_H1);
    cudaGetSymbolAddress((void**)&pH,  g_H);
    cudaGetSymbolAddress((void**)&pXL, g_XL);
    cudaGetSymbolAddress((void**)&pXR, g_XR);
    cudaGetSymbolAddress((void**)&pC1, g_C1);
    cudaGetSymbolAddress((void**)&pC2, g_C2);

    // CSR build
    zero_deg_kernel<<<(Nn + 255) / 256, 256>>>();
    count_kernel<<<(EP + 255) / 256, 256>>>(ei);
    scan_kernel<<<1, 1024>>>();
    scatter_kernel<<<(EP + 255) / 256, 256>>>(ei);

    const int MB = (Nn + 127) / 128;   // 157 row-blocks

    // encoder
    gemm_tf32_kernel<<<dim3(512 / 64, MB), 256>>>(x,   enc_w1, enc_b1, pH1, Nn, 512, 64, 1);
    gemm_tf32_kernel<<<dim3(64  / 64, MB), 256>>>(pH1, enc_w2, enc_b2, pH,  Nn, 64, 512, 1);

    // conv1
    gemm_tf32_kernel<<<dim3(256 / 64, MB), 256>>>(pH, wl1, bl1, pXL, Nn, 256, 64, 0);
    gemm_tf32_kernel<<<dim3(256 / 64, MB), 256>>>(pH, wr1, br1, pXR, Nn, 256, 64, 0);
    gat_agg_kernel<<<Nn / 8, 256>>>(pXL, pXR, att1, bias1, pC1);

    // conv2
    gemm_tf32_kernel<<<dim3(256 / 64, MB), 256>>>(pC1, wl2, bl2, pXL, Nn, 256, 256, 0);
    gemm_tf32_kernel<<<dim3(256 / 64, MB), 256>>>(pC1, wr2, br2, pXR, Nn, 256, 256, 0);
    gat_agg_kernel<<<Nn / 8, 256>>>(pXL, pXR, att2, bias2, pC2);

    // head
    gather_feat_kernel<<<(Bb * CAT + 255) / 256, 256>>>(indices);
    duel_kernel<<<Bb, 128>>>(qw1, qb1, qw2, qb2, vw1, vb1, vw2, vb2, (float*)d_out);
}

// round 4
// speedup vs baseline: 1.3839x; 1.0630x over previous
#include <cuda_runtime.h>
#include <cuda_bf16.h>

#define Nn 20000
#define Ee 320000
#define EP (Ee + Nn)      // edges + self loops = 340000
#define Bb 128
#define CAT 576

// ---------------- scratch (static __device__, no allocation) ----------------
__device__ float g_H1[Nn * 512];      // encoder hidden
__device__ float g_H [Nn * 64];       // encoder out
__device__ float g_XL[Nn * 256];      // per-layer source transform (reused)
__device__ float g_XR[Nn * 256];      // per-layer target transform (reused)
__device__ float g_C1[Nn * 256];      // conv1 out (relu)
__device__ float g_C2[Nn * 256];      // conv2 out (relu)
__device__ int   g_deg[Nn];
__device__ int   g_rowptr[Nn + 1];
__device__ int   g_cursor[Nn];
__device__ int   g_col[EP];
__device__ float g_feat[Bb * CAT];

// ---------------- 3xTF32 tensor-core GEMM, presplit in smem ------------------
// C[M,N] = act(A[M,K] @ W[K,N] + bias[N]); hi/lo tf32 split done ONCE at the
// gmem->smem copy; inner loop is pure LDS + HMMA.
__device__ __forceinline__ void mma_tf32(float c[4],
                                         const unsigned a[4], const unsigned b[2]) {
    asm volatile(
        "mma.sync.aligned.m16n8k8.row.col.f32.tf32.tf32.f32 "
        "{%0,%1,%2,%3}, {%4,%5,%6,%7}, {%8,%9}, {%0,%1,%2,%3};\n"
        : "+f"(c[0]), "+f"(c[1]), "+f"(c[2]), "+f"(c[3])
        : "r"(a[0]), "r"(a[1]), "r"(a[2]), "r"(a[3]),
          "r"(b[0]), "r"(b[1]));
}

__device__ __forceinline__ unsigned f2tf32(float f) {
    unsigned u;
    asm("cvt.rna.tf32.f32 %0, %1;\n" : "=r"(u) : "f"(f));
    return u;
}

__device__ __forceinline__ void split_tf32(float f, unsigned& hi, unsigned& lo) {
    hi = f2tf32(f);
    lo = f2tf32(f - __uint_as_float(hi));
}

__global__ __launch_bounds__(256) void gemm_tf32_kernel(
    const float* __restrict__ A, const float* __restrict__ W,
    const float* __restrict__ bias, float* __restrict__ C,
    int M, int N, int K, int do_relu)
{
    __shared__ unsigned AsH[128][36], AsL[128][36];   // [m][k]
    __shared__ unsigned BsH[32][72],  BsL[32][72];    // [k][n]

    const int tid  = threadIdx.x;
    const int warp = tid >> 5, lane = tid & 31;
    const int wm = warp & 3, wn = warp >> 2;     // warp tile: m = wm*32, n = wn*32
    const int lr = lane >> 2;                     // 0..7
    const int lc = lane & 3;                      // 0..3
    const int row0 = blockIdx.y * 128, col0 = blockIdx.x * 64;

    float acc[2][4][4];
#pragma unroll
    for (int mt = 0; mt < 2; mt++)
#pragma unroll
        for (int nt = 0; nt < 4; nt++)
#pragma unroll
            for (int i = 0; i < 4; i++) acc[mt][nt][i] = 0.f;

    for (int k0 = 0; k0 < K; k0 += 32) {
        // A tile: 128 rows x 32 cols, split on the fly
#pragma unroll
        for (int i = tid; i < 1024; i += 256) {
            int r = i >> 3, c4 = i & 7;
            int gr = min(row0 + r, M - 1);
            float4 v = *(const float4*)(A + (size_t)gr * K + k0 + c4 * 4);
            unsigned h0, l0, h1, l1, h2, l2, h3, l3;
            split_tf32(v.x, h0, l0); split_tf32(v.y, h1, l1);
            split_tf32(v.z, h2, l2); split_tf32(v.w, h3, l3);
            int c = c4 * 4;
            AsH[r][c] = h0; AsH[r][c+1] = h1; AsH[r][c+2] = h2; AsH[r][c+3] = h3;
            AsL[r][c] = l0; AsL[r][c+1] = l1; AsL[r][c+2] = l2; AsL[r][c+3] = l3;
        }
        // B tile: 32 rows x 64 cols
#pragma unroll
        for (int i = tid; i < 512; i += 256) {
            int r = i >> 4, c4 = i & 15;
            float4 v = *(const float4*)(W + (size_t)(k0 + r) * N + col0 + c4 * 4);
            unsigned h0, l0, h1, l1, h2, l2, h3, l3;
            split_tf32(v.x, h0, l0); split_tf32(v.y, h1, l1);
            split_tf32(v.z, h2, l2); split_tf32(v.w, h3, l3);
            int c = c4 * 4;
            BsH[r][c] = h0; BsH[r][c+1] = h1; BsH[r][c+2] = h2; BsH[r][c+3] = h3;
            BsL[r][c] = l0; BsL[r][c+1] = l1; BsL[r][c+2] = l2; BsL[r][c+3] = l3;
        }
        __syncthreads();

#pragma unroll
        for (int kk = 0; kk < 32; kk += 8) {
            unsigned ahi[2][4], alo[2][4];
#pragma unroll
            for (int mt = 0; mt < 2; mt++) {
                int r = wm * 32 + mt * 16 + lr;
                ahi[mt][0] = AsH[r][kk + lc];
                ahi[mt][1] = AsH[r + 8][kk + lc];
                ahi[mt][2] = AsH[r][kk + lc + 4];
                ahi[mt][3] = AsH[r + 8][kk + lc + 4];
                alo[mt][0] = AsL[r][kk + lc];
                alo[mt][1] = AsL[r + 8][kk + lc];
                alo[mt][2] = AsL[r][kk + lc + 4];
                alo[mt][3] = AsL[r + 8][kk + lc + 4];
            }
            unsigned bhi[4][2], blo[4][2];
#pragma unroll
            for (int nt = 0; nt < 4; nt++) {
                int n = wn * 32 + nt * 8 + lr;
                bhi[nt][0] = BsH[kk + lc][n];
                bhi[nt][1] = BsH[kk + lc + 4][n];
                blo[nt][0] = BsL[kk + lc][n];
                blo[nt][1] = BsL[kk + lc + 4][n];
            }
#pragma unroll
            for (int mt = 0; mt < 2; mt++)
#pragma unroll
                for (int nt = 0; nt < 4; nt++) {
                    mma_tf32(acc[mt][nt], ahi[mt], blo[nt]);
                    mma_tf32(acc[mt][nt], alo[mt], bhi[nt]);
                    mma_tf32(acc[mt][nt], ahi[mt], bhi[nt]);
                }
        }
        __syncthreads();
    }

    // epilogue: c0 (r, 2lc) c1 (r, 2lc+1) c2 (r+8, 2lc) c3 (r+8, 2lc+1)
#pragma unroll
    for (int mt = 0; mt < 2; mt++) {
#pragma unroll
        for (int nt = 0; nt < 4; nt++) {
            int r = row0 + wm * 32 + mt * 16 + lr;
            int n = col0 + wn * 32 + nt * 8 + 2 * lc;
            float b0 = bias[n], b1 = bias[n + 1];
            float v0 = acc[mt][nt][0] + b0, v1 = acc[mt][nt][1] + b1;
            float v2 = acc[mt][nt][2] + b0, v3 = acc[mt][nt][3] + b1;
            if (do_relu) {
                v0 = fmaxf(v0, 0.f); v1 = fmaxf(v1, 0.f);
                v2 = fmaxf(v2, 0.f); v3 = fmaxf(v3, 0.f);
            }
            if (r < M)     *(float2*)(C + (size_t)r * N + n)       = make_float2(v0, v1);
            if (r + 8 < M) *(float2*)(C + (size_t)(r + 8) * N + n) = make_float2(v2, v3);
        }
    }
}

// ---------------- CSR build ----------------
__global__ void zero_deg_kernel() {
    int i = blockIdx.x * blockDim.x + threadIdx.x;
    if (i < Nn) g_deg[i] = 0;
}

__global__ void count_kernel(const int* __restrict__ ei) {
    int e = blockIdx.x * blockDim.x + threadIdx.x;
    if (e >= EP) return;
    int d = (e < Ee) ? ei[Ee + e] : (e - Ee);
    atomicAdd(&g_deg[d], 1);
}

__global__ __launch_bounds__(1024) void scan_kernel() {
    __shared__ int s[1024];
    int tid = threadIdx.x;
    const int chunk = (Nn + 1023) / 1024;   // 20
    int start = tid * chunk;
    int sum = 0;
    for (int i = 0; i < chunk; i++) {
        int idx = start + i;
        if (idx < Nn) sum += g_deg[idx];
    }
    s[tid] = sum;
    __syncthreads();
    for (int off = 1; off < 1024; off <<= 1) {
        int v = (tid >= off) ? s[tid - off] : 0;
        __syncthreads();
        s[tid] += v;
        __syncthreads();
    }
    int run = (tid > 0) ? s[tid - 1] : 0;
    for (int i = 0; i < chunk; i++) {
        int idx = start + i;
        if (idx < Nn) { g_rowptr[idx] = run; g_cursor[idx] = run; run += g_deg[idx]; }
    }
    if (tid == 1023) g_rowptr[Nn] = s[1023];
}

__global__ void scatter_kernel(const int* __restrict__ ei) {
    int e = blockIdx.x * blockDim.x + threadIdx.x;
    if (e >= EP) return;
    int s, d;
    if (e < Ee) { s = ei[e]; d = ei[Ee + e]; }
    else        { s = e - Ee; d = s; }
    int pos = atomicAdd(&g_cursor[d], 1);
    g_col[pos] = s;
}

// ------- GATv2 aggregation: one warp per dst node, single-pass online softmax
__device__ __forceinline__ float lrelu(float v) { return v > 0.f ? v : 0.2f * v; }

__global__ __launch_bounds__(256) void gat_agg_kernel(
    const float* __restrict__ XL, const float* __restrict__ XR,
    const float* __restrict__ att, const float* __restrict__ bias,
    float* __restrict__ OUT)
{
    int warp = (blockIdx.x * blockDim.x + threadIdx.x) >> 5;
    if (warp >= Nn) return;
    int lane = threadIdx.x & 31;

    // lane covers dims [lane*8, lane*8+8); head = lane/8 (HID=64 dims = 8 lanes)
    const float4* xr4 = reinterpret_cast<const float4*>(XR + (size_t)warp * 256 + lane * 8);
    float4 xr0 = xr4[0], xr1 = xr4[1];
    const float4* at4 = reinterpret_cast<const float4*>(att + lane * 8);
    float4 at0 = at4[0], at1 = at4[1];

    int s0 = g_rowptr[warp], s1 = g_rowptr[warp + 1];

    float m = -3.0e38f, denom = 0.f;
    float acc[8] = {0.f, 0.f, 0.f, 0.f, 0.f, 0.f, 0.f, 0.f};

    for (int slot = s0; slot < s1; slot++) {
        int src = g_col[slot];
        const float4* xl4 = reinterpret_cast<const float4*>(XL + (size_t)src * 256 + lane * 8);
        float4 a = xl4[0], b = xl4[1];
        float p = 0.f;
        p = fmaf(at0.x, lrelu(a.x + xr0.x), p);
        p = fmaf(at0.y, lrelu(a.y + xr0.y), p);
        p = fmaf(at0.z, lrelu(a.z + xr0.z), p);
        p = fmaf(at0.w, lrelu(a.w + xr0.w), p);
        p = fmaf(at1.x, lrelu(b.x + xr1.x), p);
        p = fmaf(at1.y, lrelu(b.y + xr1.y), p);
        p = fmaf(at1.z, lrelu(b.z + xr1.z), p);
        p = fmaf(at1.w, lrelu(b.w + xr1.w), p);
        p += __shfl_xor_sync(0xffffffffu, p, 1);
        p += __shfl_xor_sync(0xffffffffu, p, 2);
        p += __shfl_xor_sync(0xffffffffu, p, 4);

        // online softmax update
        float mnew = fmaxf(m, p);
        float sc = __expf(m - mnew);   // ==1 when no new max; ==0 on first edge
        float ex = __expf(p - mnew);
        m = mnew;
        denom = denom * sc + ex;
        acc[0] = fmaf(ex, a.x, acc[0] * sc);
        acc[1] = fmaf(ex, a.y, acc[1] * sc);
        acc[2] = fmaf(ex, a.z, acc[2] * sc);
        acc[3] = fmaf(ex, a.w, acc[3] * sc);
        acc[4] = fmaf(ex, b.x, acc[4] * sc);
        acc[5] = fmaf(ex, b.y, acc[5] * sc);
        acc[6] = fmaf(ex, b.z, acc[6] * sc);
        acc[7] = fmaf(ex, b.w, acc[7] * sc);
    }

    float inv = 1.0f / (denom + 1e-16f);
    const float4* bi4 = reinterpret_cast<const float4*>(bias + lane * 8);
    float4 bb0 = bi4[0], bb1 = bi4[1];
    float4 o0, o1;
    o0.x = fmaxf(acc[0] * inv + bb0.x, 0.f);
    o0.y = fmaxf(acc[1] * inv + bb0.y, 0.f);
    o0.z = fmaxf(acc[2] * inv + bb0.z, 0.f);
    o0.w = fmaxf(acc[3] * inv + bb0.w, 0.f);
    o1.x = fmaxf(acc[4] * inv + bb1.x, 0.f);
    o1.y = fmaxf(acc[5] * inv + bb1.y, 0.f);
    o1.z = fmaxf(acc[6] * inv + bb1.z, 0.f);
    o1.w = fmaxf(acc[7] * inv + bb1.w, 0.f);
    float4* out4 = reinterpret_cast<float4*>(OUT + (size_t)warp * 256 + lane * 8);
    out4[0] = o0;
    out4[1] = o1;
}

// ---------------- batch gather + dueling head ----------------
__global__ void gather_feat_kernel(const int* __restrict__ idx) {
    int i = blockIdx.x * blockDim.x + threadIdx.x;
    if (i >= Bb * CAT) return;
    int b = i / CAT, j = i % CAT;
    int node = idx[b];
    float v;
    if (j < 64)       v = g_H [node * 64 + j];
    else if (j < 320) v = g_C1[node * 256 + (j - 64)];
    else              v = g_C2[node * 256 + (j - 320)];
    g_feat[i] = v;
}

__global__ __launch_bounds__(128) void duel_kernel(
    const float* __restrict__ qw1, const float* __restrict__ qb1,
    const float* __restrict__ qw2, const float* __restrict__ qb2,
    const float* __restrict__ vw1, const float* __restrict__ vb1,
    const float* __restrict__ vw2, const float* __restrict__ vb2,
    float* __restrict__ out)
{
    int b = blockIdx.x;
    int t = threadIdx.x;
    __shared__ float f[CAT];
    __shared__ float r0[128], r1[128], rv[128];
    for (int i = t; i < CAT; i += 128) f[i] = g_feat[b * CAT + i];
    __syncthreads();

    float sq = qb1[t], sv = vb1[t];
    for (int j = 0; j < CAT; j++) {
        float fv = f[j];
        sq = fmaf(fv, qw1[j * 128 + t], sq);
        sv = fmaf(fv, vw1[j * 128 + t], sv);
    }
    sq = fmaxf(sq, 0.f);
    sv = fmaxf(sv, 0.f);
    r0[t] = sq * qw2[t * 2 + 0];
    r1[t] = sq * qw2[t * 2 + 1];
    rv[t] = sv * vw2[t];
    __syncthreads();
    for (int off = 64; off > 0; off >>= 1) {
        if (t < off) {
            r0[t] += r0[t + off];
            r1[t] += r1[t + off];
            rv[t] += rv[t + off];
        }
        __syncthreads();
    }
    if (t == 0) {
        float q0 = r0[0] + qb2[0];
        float q1 = r1[0] + qb2[1];
        float v  = rv[0] + vb2[0];
        float mth = 0.5f * (q0 + q1);
        out[b * 2 + 0] = q0 - mth + v;
        out[b * 2 + 1] = q1 - mth + v;
    }
}

// ---------------- host ----------------
extern "C" void kernel_launch(void* const* d_in, const int* in_sizes, int n_in,
                              void* d_out, int out_size)
{
    const float* x       = (const float*)d_in[0];
    const int*   ei      = (const int*)  d_in[1];
    const int*   indices = (const int*)  d_in[2];
    const float* enc_w1 = (const float*)d_in[3],  *enc_b1 = (const float*)d_in[4];
    const float* enc_w2 = (const float*)d_in[5],  *enc_b2 = (const float*)d_in[6];
    const float* wl1 = (const float*)d_in[7],  *bl1 = (const float*)d_in[8];
    const float* wr1 = (const float*)d_in[9],  *br1 = (const float*)d_in[10];
    const float* att1 = (const float*)d_in[11], *bias1 = (const float*)d_in[12];
    const float* wl2 = (const float*)d_in[13], *bl2 = (const float*)d_in[14];
    const float* wr2 = (const float*)d_in[15], *br2 = (const float*)d_in[16];
    const float* att2 = (const float*)d_in[17], *bias2 = (const float*)d_in[18];
    const float* qw1 = (const float*)d_in[19], *qb1 = (const float*)d_in[20];
    const float* qw2 = (const float*)d_in[21], *qb2 = (const float*)d_in[22];
    const float* vw1 = (const float*)d_in[23], *vb1 = (const float*)d_in[24];
    const float* vw2 = (const float*)d_in[25], *vb2 = (const float*)d_in[26];

    float *pH1, *pH, *pXL, *pXR, *pC1, *pC2;
    cudaGetSymbolAddress((void**)&pH1, g_H1);
    cudaGetSymbolAddress((void**)&pH,  g_H);
    cudaGetSymbolAddress((void**)&pXL, g_XL);
    cudaGetSymbolAddress((void**)&pXR, g_XR);
    cudaGetSymbolAddress((void**)&pC1, g_C1);
    cudaGetSymbolAddress((void**)&pC2, g_C2);

    // CSR build
    zero_deg_kernel<<<(Nn + 255) / 256, 256>>>();
    count_kernel<<<(EP + 255) / 256, 256>>>(ei);
    scan_kernel<<<1, 1024>>>();
    scatter_kernel<<<(EP + 255) / 256, 256>>>(ei);

    const int MB = (Nn + 127) / 128;   // 157 row-blocks

    // encoder
    gemm_tf32_kernel<<<dim3(512 / 64, MB), 256>>>(x,   enc_w1, enc_b1, pH1, Nn, 512, 64, 1);
    gemm_tf32_kernel<<<dim3(64  / 64, MB), 256>>>(pH1, enc_w2, enc_b2, pH,  Nn, 64, 512, 1);

    // conv1
    gemm_tf32_kernel<<<dim3(256 / 64, MB), 256>>>(pH, wl1, bl1, pXL, Nn, 256, 64, 0);
    gemm_tf32_kernel<<<dim3(256 / 64, MB), 256>>>(pH, wr1, br1, pXR, Nn, 256, 64, 0);
    gat_agg_kernel<<<Nn / 8, 256>>>(pXL, pXR, att1, bias1, pC1);

    // conv2
    gemm_tf32_kernel<<<dim3(256 / 64, MB), 256>>>(pC1, wl2, bl2, pXL, Nn, 256, 256, 0);
    gemm_tf32_kernel<<<dim3(256 / 64, MB), 256>>>(pC1, wr2, br2, pXR, Nn, 256, 256, 0);
    gat_agg_kernel<<<Nn / 8, 256>>>(pXL, pXR, att2, bias2, pC2);

    // head
    gather_feat_kernel<<<(Bb * CAT + 255) / 256, 256>>>(indices);
    duel_kernel<<<Bb, 128>>>(qw1, qb1, qw2, qb2, vw1, vb1, vw2, vb2, (float*)d_out);
}

// round 5
// speedup vs baseline: 1.6156x; 1.1675x over previous
#include <cuda_runtime.h>
#include <cuda_bf16.h>

#define Nn 20000
#define Ee 320000
#define EP (Ee + Nn)      // edges + self loops = 340000
#define Bb 128
#define CAT 576

// ---------------- scratch (static __device__, no allocation) ----------------
__device__ float g_H1[Nn * 512];      // encoder hidden
__device__ float g_H [Nn * 64];       // encoder out
__device__ float g_XL[Nn * 256];
__device__ float g_XR[Nn * 256];
__device__ float g_C1[Nn * 256];
__device__ float g_C2[Nn * 256];
__device__ int   g_deg[Nn];
__device__ int   g_rowptr[Nn + 1];
__device__ int   g_cursor[Nn];
__device__ int   g_col[EP];
__device__ float g_feat[Bb * CAT];
// transposed + bf16-split weight scratch (per-GEMM, reused sequentially)
__device__ __align__(16) __nv_bfloat16 g_WT_hi[65536];
__device__ __align__(16) __nv_bfloat16 g_WT_lo[65536];

// ---------------- weight transpose + bf16 split ------------------------------
// WT_hi/lo[n*K + k] = split(W[k*N + n])
__global__ void transpose_split_kernel(const float* __restrict__ W, int K, int N) {
    int i = blockIdx.x * blockDim.x + threadIdx.x;
    if (i >= K * N) return;
    int n = i / K, k = i % K;
    float f = W[(size_t)k * N + n];
    __nv_bfloat16 h = __float2bfloat16(f);
    g_WT_hi[i] = h;
    g_WT_lo[i] = __float2bfloat16(f - __bfloat162float(h));
}

// ---------------- 3-term bf16 tensor-core GEMM -------------------------------
// C[M,N] = act(A @ W + bias); A split to bf16 hi/lo at smem store; W presplit
// in gmem (transposed).  c += a_hi*b_lo + a_lo*b_hi + a_hi*b_hi, fp32 accum.
__device__ __forceinline__ void mma_bf16(float c[4],
                                         const unsigned a[4], const unsigned b[2]) {
    asm volatile(
        "mma.sync.aligned.m16n8k16.row.col.f32.bf16.bf16.f32 "
        "{%0,%1,%2,%3}, {%4,%5,%6,%7}, {%8,%9}, {%0,%1,%2,%3};\n"
        : "+f"(c[0]), "+f"(c[1]), "+f"(c[2]), "+f"(c[3])
        : "r"(a[0]), "r"(a[1]), "r"(a[2]), "r"(a[3]),
          "r"(b[0]), "r"(b[1]));
}

__device__ __forceinline__ unsigned pack_hi2(float x, float y) {
    __nv_bfloat162 v = __floats2bfloat162_rn(x, y);
    return *reinterpret_cast<unsigned*>(&v);
}

__global__ __launch_bounds__(256) void gemm_bf16x2_kernel(
    const float* __restrict__ A,
    const float* __restrict__ bias, float* __restrict__ C,
    int M, int N, int K, int do_relu)
{
    // k-chunk 32 = 16 bf16x2 per row, pad to 20 words
    __shared__ unsigned AsH[128][20], AsL[128][20];   // [m][k2]
    __shared__ unsigned BsH[64][20],  BsL[64][20];    // [n][k2]

    const int tid  = threadIdx.x;
    const int warp = tid >> 5, lane = tid & 31;
    const int wm = warp & 3, wn = warp >> 2;     // warp tile 32(m) x 32(n)
    const int lr = lane >> 2;                     // 0..7
    const int lc = lane & 3;                      // 0..3
    const int row0 = blockIdx.y * 128, col0 = blockIdx.x * 64;

    float acc[2][4][4];
#pragma unroll
    for (int mt = 0; mt < 2; mt++)
#pragma unroll
        for (int nt = 0; nt < 4; nt++)
#pragma unroll
            for (int i = 0; i < 4; i++) acc[mt][nt][i] = 0.f;

    for (int k0 = 0; k0 < K; k0 += 32) {
        // A tile: 128 rows x 32 k (fp32), split on the fly. 1024 float4 loads.
#pragma unroll
        for (int i = tid; i < 1024; i += 256) {
            int r = i >> 3, c4 = i & 7;           // c4: float4 index (4 k vals)
            int gr = min(row0 + r, M - 1);
            float4 v = *(const float4*)(A + (size_t)gr * K + k0 + c4 * 4);
            float hx = __bfloat162float(__float2bfloat16(v.x));
            float hy = __bfloat162float(__float2bfloat16(v.y));
            float hz = __bfloat162float(__float2bfloat16(v.z));
            float hw = __bfloat162float(__float2bfloat16(v.w));
            AsH[r][c4 * 2]     = pack_hi2(hx, hy);
            AsH[r][c4 * 2 + 1] = pack_hi2(hz, hw);
            AsL[r][c4 * 2]     = pack_hi2(v.x - hx, v.y - hy);
            AsL[r][c4 * 2 + 1] = pack_hi2(v.z - hz, v.w - hw);
        }
        // B tile: 64 n-rows x 32 k bf16 from presplit W^T. 16B per (row, half);
        // 64 rows * 2 uint4 per row per array = 128 loads each.
#pragma unroll
        for (int i = tid; i < 256; i += 256) {
            int r = i >> 2, q = i & 3;            // q: which 8-bf16 group
            const uint4* sh = (const uint4*)(g_WT_hi + (size_t)(col0 + r) * K + k0 + q * 8);
            const uint4* sl = (const uint4*)(g_WT_lo + (size_t)(col0 + r) * K + k0 + q * 8);
            *(uint4*)&BsH[r][q * 4] = *sh;
            *(uint4*)&BsL[r][q * 4] = *sl;
        }
        __syncthreads();

#pragma unroll
        for (int s = 0; s < 2; s++) {             // two k16 steps per chunk
            const int kb = s * 8;
            unsigned ahi[2][4], alo[2][4];
#pragma unroll
            for (int mt = 0; mt < 2; mt++) {
                int r = wm * 32 + mt * 16 + lr;
                ahi[mt][0] = AsH[r][kb + lc];
                ahi[mt][1] = AsH[r + 8][kb + lc];
                ahi[mt][2] = AsH[r][kb + lc + 4];
                ahi[mt][3] = AsH[r + 8][kb + lc + 4];
                alo[mt][0] = AsL[r][kb + lc];
                alo[mt][1] = AsL[r + 8][kb + lc];
                alo[mt][2] = AsL[r][kb + lc + 4];
                alo[mt][3] = AsL[r + 8][kb + lc + 4];
            }
            unsigned bhi[4][2], blo[4][2];
#pragma unroll
            for (int nt = 0; nt < 4; nt++) {
                int n = wn * 32 + nt * 8 + lr;
                bhi[nt][0] = BsH[n][kb + lc];
                bhi[nt][1] = BsH[n][kb + lc + 4];
                blo[nt][0] = BsL[n][kb + lc];
                blo[nt][1] = BsL[n][kb + lc + 4];
            }
#pragma unroll
            for (int mt = 0; mt < 2; mt++)
#pragma unroll
                for (int nt = 0; nt < 4; nt++) {
                    mma_bf16(acc[mt][nt], ahi[mt], blo[nt]);
                    mma_bf16(acc[mt][nt], alo[mt], bhi[nt]);
                    mma_bf16(acc[mt][nt], ahi[mt], bhi[nt]);
                }
        }
        __syncthreads();
    }

    // epilogue: c0 (r, 2lc) c1 (r, 2lc+1) c2 (r+8, 2lc) c3 (r+8, 2lc+1)
#pragma unroll
    for (int mt = 0; mt < 2; mt++) {
#pragma unroll
        for (int nt = 0; nt < 4; nt++) {
            int r = row0 + wm * 32 + mt * 16 + lr;
            int n = col0 + wn * 32 + nt * 8 + 2 * lc;
            float b0 = bias[n], b1 = bias[n + 1];
            float v0 = acc[mt][nt][0] + b0, v1 = acc[mt][nt][1] + b1;
            float v2 = acc[mt][nt][2] + b0, v3 = acc[mt][nt][3] + b1;
            if (do_relu) {
                v0 = fmaxf(v0, 0.f); v1 = fmaxf(v1, 0.f);
                v2 = fmaxf(v2, 0.f); v3 = fmaxf(v3, 0.f);
            }
            if (r < M)     *(float2*)(C + (size_t)r * N + n)       = make_float2(v0, v1);
            if (r + 8 < M) *(float2*)(C + (size_t)(r + 8) * N + n) = make_float2(v2, v3);
        }
    }
}

// ---------------- CSR build ----------------
__global__ void zero_deg_kernel() {
    int i = blockIdx.x * blockDim.x + threadIdx.x;
    if (i < Nn) g_deg[i] = 0;
}

__global__ void count_kernel(const int* __restrict__ ei) {
    int e = blockIdx.x * blockDim.x + threadIdx.x;
    if (e >= EP) return;
    int d = (e < Ee) ? ei[Ee + e] : (e - Ee);
    atomicAdd(&g_deg[d], 1);
}

__global__ __launch_bounds__(1024) void scan_kernel() {
    __shared__ int s[1024];
    int tid = threadIdx.x;
    const int chunk = (Nn + 1023) / 1024;
    int start = tid * chunk;
    int sum = 0;
    for (int i = 0; i < chunk; i++) {
        int idx = start + i;
        if (idx < Nn) sum += g_deg[idx];
    }
    s[tid] = sum;
    __syncthreads();
    for (int off = 1; off < 1024; off <<= 1) {
        int v = (tid >= off) ? s[tid - off] : 0;
        __syncthreads();
        s[tid] += v;
        __syncthreads();
    }
    int run = (tid > 0) ? s[tid - 1] : 0;
    for (int i = 0; i < chunk; i++) {
        int idx = start + i;
        if (idx < Nn) { g_rowptr[idx] = run; g_cursor[idx] = run; run += g_deg[idx]; }
    }
    if (tid == 1023) g_rowptr[Nn] = s[1023];
}

__global__ void scatter_kernel(const int* __restrict__ ei) {
    int e = blockIdx.x * blockDim.x + threadIdx.x;
    if (e >= EP) return;
    int s, d;
    if (e < Ee) { s = ei[e]; d = ei[Ee + e]; }
    else        { s = e - Ee; d = s; }
    int pos = atomicAdd(&g_cursor[d], 1);
    g_col[pos] = s;
}

// ------- GATv2 aggregation: one warp per dst node, single-pass online softmax
__device__ __forceinline__ float lrelu(float v) { return v > 0.f ? v : 0.2f * v; }

__global__ __launch_bounds__(256) void gat_agg_kernel(
    const float* __restrict__ XL, const float* __restrict__ XR,
    const float* __restrict__ att, const float* __restrict__ bias,
    float* __restrict__ OUT)
{
    int warp = (blockIdx.x * blockDim.x + threadIdx.x) >> 5;
    if (warp >= Nn) return;
    int lane = threadIdx.x & 31;

    const float4* xr4 = reinterpret_cast<const float4*>(XR + (size_t)warp * 256 + lane * 8);
    float4 xr0 = xr4[0], xr1 = xr4[1];
    const float4* at4 = reinterpret_cast<const float4*>(att + lane * 8);
    float4 at0 = at4[0], at1 = at4[1];

    int s0 = g_rowptr[warp], s1 = g_rowptr[warp + 1];

    float m = -3.0e38f, denom = 0.f;
    float acc[8] = {0.f, 0.f, 0.f, 0.f, 0.f, 0.f, 0.f, 0.f};

    for (int slot = s0; slot < s1; slot++) {
        int src = g_col[slot];
        const float4* xl4 = reinterpret_cast<const float4*>(XL + (size_t)src * 256 + lane * 8);
        float4 a = xl4[0], b = xl4[1];
        float p = 0.f;
        p = fmaf(at0.x, lrelu(a.x + xr0.x), p);
        p = fmaf(at0.y, lrelu(a.y + xr0.y), p);
        p = fmaf(at0.z, lrelu(a.z + xr0.z), p);
        p = fmaf(at0.w, lrelu(a.w + xr0.w), p);
        p = fmaf(at1.x, lrelu(b.x + xr1.x), p);
        p = fmaf(at1.y, lrelu(b.y + xr1.y), p);
        p = fmaf(at1.z, lrelu(b.z + xr1.z), p);
        p = fmaf(at1.w, lrelu(b.w + xr1.w), p);
        p += __shfl_xor_sync(0xffffffffu, p, 1);
        p += __shfl_xor_sync(0xffffffffu, p, 2);
        p += __shfl_xor_sync(0xffffffffu, p, 4);

        float mnew = fmaxf(m, p);
        float sc = __expf(m - mnew);
        float ex = __expf(p - mnew);
        m = mnew;
        denom = denom * sc + ex;
        acc[0] = fmaf(ex, a.x, acc[0] * sc);
        acc[1] = fmaf(ex, a.y, acc[1] * sc);
        acc[2] = fmaf(ex, a.z, acc[2] * sc);
        acc[3] = fmaf(ex, a.w, acc[3] * sc);
        acc[4] = fmaf(ex, b.x, acc[4] * sc);
        acc[5] = fmaf(ex, b.y, acc[5] * sc);
        acc[6] = fmaf(ex, b.z, acc[6] * sc);
        acc[7] = fmaf(ex, b.w, acc[7] * sc);
    }

    float inv = 1.0f / (denom + 1e-16f);
    const float4* bi4 = reinterpret_cast<const float4*>(bias + lane * 8);
    float4 bb0 = bi4[0], bb1 = bi4[1];
    float4 o0, o1;
    o0.x = fmaxf(acc[0] * inv + bb0.x, 0.f);
    o0.y = fmaxf(acc[1] * inv + bb0.y, 0.f);
    o0.z = fmaxf(acc[2] * inv + bb0.z, 0.f);
    o0.w = fmaxf(acc[3] * inv + bb0.w, 0.f);
    o1.x = fmaxf(acc[4] * inv + bb1.x, 0.f);
    o1.y = fmaxf(acc[5] * inv + bb1.y, 0.f);
    o1.z = fmaxf(acc[6] * inv + bb1.z, 0.f);
    o1.w = fmaxf(acc[7] * inv + bb1.w, 0.f);
    float4* out4 = reinterpret_cast<float4*>(OUT + (size_t)warp * 256 + lane * 8);
    out4[0] = o0;
    out4[1] = o1;
}

// ---------------- batch gather + dueling head ----------------
__global__ void gather_feat_kernel(const int* __restrict__ idx) {
    int i = blockIdx.x * blockDim.x + threadIdx.x;
    if (i >= Bb * CAT) return;
    int b = i / CAT, j = i % CAT;
    int node = idx[b];
    float v;
    if (j < 64)       v = g_H [node * 64 + j];
    else if (j < 320) v = g_C1[node * 256 + (j - 64)];
    else              v = g_C2[node * 256 + (j - 320)];
    g_feat[i] = v;
}

__global__ __launch_bounds__(128) void duel_kernel(
    const float* __restrict__ qw1, const float* __restrict__ qb1,
    const float* __restrict__ qw2, const float* __restrict__ qb2,
    const float* __restrict__ vw1, const float* __restrict__ vb1,
    const float* __restrict__ vw2, const float* __restrict__ vb2,
    float* __restrict__ out)
{
    int b = blockIdx.x;
    int t = threadIdx.x;
    __shared__ float f[CAT];
    __shared__ float r0[128], r1[128], rv[128];
    for (int i = t; i < CAT; i += 128) f[i] = g_feat[b * CAT + i];
    __syncthreads();

    float sq = qb1[t], sv = vb1[t];
    for (int j = 0; j < CAT; j++) {
        float fv = f[j];
        sq = fmaf(fv, qw1[j * 128 + t], sq);
        sv = fmaf(fv, vw1[j * 128 + t], sv);
    }
    sq = fmaxf(sq, 0.f);
    sv = fmaxf(sv, 0.f);
    r0[t] = sq * qw2[t * 2 + 0];
    r1[t] = sq * qw2[t * 2 + 1];
    rv[t] = sv * vw2[t];
    __syncthreads();
    for (int off = 64; off > 0; off >>= 1) {
        if (t < off) {
            r0[t] += r0[t + off];
            r1[t] += r1[t + off];
            rv[t] += rv[t + off];
        }
        __syncthreads();
    }
    if (t == 0) {
        float q0 = r0[0] + qb2[0];
        float q1 = r1[0] + qb2[1];
        float v  = rv[0] + vb2[0];
        float mth = 0.5f * (q0 + q1);
        out[b * 2 + 0] = q0 - mth + v;
        out[b * 2 + 1] = q1 - mth + v;
    }
}

// ---------------- host ----------------
static inline void run_gemm(const float* A, const float* W, const float* bias,
                            float* C, int M, int N, int K, int relu)
{
    transpose_split_kernel<<<(K * N + 255) / 256, 256>>>(W, K, N);
    gemm_bf16x2_kernel<<<dim3(N / 64, (M + 127) / 128), 256>>>(A, bias, C, M, N, K, relu);
}

extern "C" void kernel_launch(void* const* d_in, const int* in_sizes, int n_in,
                              void* d_out, int out_size)
{
    const float* x       = (const float*)d_in[0];
    const int*   ei      = (const int*)  d_in[1];
    const int*   indices = (const int*)  d_in[2];
    const float* enc_w1 = (const float*)d_in[3],  *enc_b1 = (const float*)d_in[4];
    const float* enc_w2 = (const float*)d_in[5],  *enc_b2 = (const float*)d_in[6];
    const float* wl1 = (const float*)d_in[7],  *bl1 = (const float*)d_in[8];
    const float* wr1 = (const float*)d_in[9],  *br1 = (const float*)d_in[10];
    const float* att1 = (const float*)d_in[11], *bias1 = (const float*)d_in[12];
    const float* wl2 = (const float*)d_in[13], *bl2 = (const float*)d_in[14];
    const float* wr2 = (const float*)d_in[15], *br2 = (const float*)d_in[16];
    const float* att2 = (const float*)d_in[17], *bias2 = (const float*)d_in[18];
    const float* qw1 = (const float*)d_in[19], *qb1 = (const float*)d_in[20];
    const float* qw2 = (const float*)d_in[21], *qb2 = (const float*)d_in[22];
    const float* vw1 = (const float*)d_in[23], *vb1 = (const float*)d_in[24];
    const float* vw2 = (const float*)d_in[25], *vb2 = (const float*)d_in[26];

    float *pH1, *pH, *pXL, *pXR, *pC1, *pC2;
    cudaGetSymbolAddress((void**)&pH1, g_H1);
    cudaGetSymbolAddress((void**)&pH,  g_H);
    cudaGetSymbolAddress((void**)&pXL, g_XL);
    cudaGetSymbolAddress((void**)&pXR, g_XR);
    cudaGetSymbolAddress((void**)&pC1, g_C1);
    cudaGetSymbolAddress((void**)&pC2, g_C2);

    // CSR build
    zero_deg_kernel<<<(Nn + 255) / 256, 256>>>();
    count_kernel<<<(EP + 255) / 256, 256>>>(ei);
    scan_kernel<<<1, 1024>>>();
    scatter_kernel<<<(EP + 255) / 256, 256>>>(ei);

    // encoder
    run_gemm(x,   enc_w1, enc_b1, pH1, Nn, 512, 64, 1);
    run_gemm(pH1, enc_w2, enc_b2, pH,  Nn, 64, 512, 1);

    // conv1
    run_gemm(pH, wl1, bl1, pXL, Nn, 256, 64, 0);
    run_gemm(pH, wr1, br1, pXR, Nn, 256, 64, 0);
    gat_agg_kernel<<<Nn / 8, 256>>>(pXL, pXR, att1, bias1, pC1);

    // conv2
    run_gemm(pC1, wl2, bl2, pXL, Nn, 256, 256, 0);
    run_gemm(pC1, wr2, br2, pXR, Nn, 256, 256, 0);
    gat_agg_kernel<<<Nn / 8, 256>>>(pXL, pXR, att2, bias2, pC2);

    // head
    gather_feat_kernel<<<(Bb * CAT + 255) / 256, 256>>>(indices);
    duel_kernel<<<Bb, 128>>>(qw1, qb1, qw2, qb2, vw1, vb1, vw2, vb2, (float*)d_out);
}